// round 11
// baseline (speedup 1.0000x reference)
#include <cuda_runtime.h>
#include <cuda_bf16.h>
#include <cstdint>

#define D  768
#define KP 256

__device__ __align__(16) uint8_t g_pn8[KP * D];    // normalized prototypes e4m3 [k][d]
__device__ __align__(16) uint8_t g_pwt8[D * KP];   // e4m3( (P@W^T)[k][e] * 64 ) : [e][k]
__device__ __align__(16) float   g_pwC[D];         // C[e] = sum_k (P@W^T)[k][e]  (exact fp32)

// ---------------------------------------------------------------------------
__device__ __forceinline__ uint32_t smem_u32(const void* p) {
    uint32_t a;
    asm("{ .reg .u64 t; cvta.to.shared.u64 t, %1; cvt.u32.u64 %0, t; }" : "=r"(a) : "l"(p));
    return a;
}
__device__ __forceinline__ uint16_t packe4m3(float lo, float hi) {
    uint16_t h;
    asm("cvt.rn.satfinite.e4m3x2.f32 %0, %1, %2;" : "=h"(h) : "f"(hi), "f"(lo));
    return h;
}
__device__ __forceinline__ void ldsm_x4(uint32_t& r0, uint32_t& r1, uint32_t& r2, uint32_t& r3,
                                        uint32_t addr) {
    asm volatile("ldmatrix.sync.aligned.m8n8.x4.shared.b16 {%0,%1,%2,%3}, [%4];"
                 : "=r"(r0), "=r"(r1), "=r"(r2), "=r"(r3) : "r"(addr));
}
__device__ __forceinline__ void mma8(float* c, uint32_t a0, uint32_t a1, uint32_t a2, uint32_t a3,
                                     uint32_t b0, uint32_t b1) {
    asm volatile(
        "mma.sync.aligned.m16n8k32.row.col.f32.e4m3.e4m3.f32 "
        "{%0,%1,%2,%3}, {%4,%5,%6,%7}, {%8,%9}, {%0,%1,%2,%3};"
        : "+f"(c[0]), "+f"(c[1]), "+f"(c[2]), "+f"(c[3])
        : "r"(a0), "r"(a1), "r"(a2), "r"(a3), "r"(b0), "r"(b1));
}
#define CP16(dst, src) asm volatile("cp.async.cg.shared.global [%0], [%1], 16;" :: "r"(dst), "l"(src))
#define CP_COMMIT()    asm volatile("cp.async.commit_group;" ::: "memory")
#define CP_WAIT0()     asm volatile("cp.async.wait_group 0;" ::: "memory")

// ---------------------------------------------------------------------------
// Merged prep: blocks [0,256) normalize prototypes -> e4m3;
//              blocks [256,448) build PW e4m3 (x64) + exact column-sum C
// ---------------------------------------------------------------------------
__global__ void prep_kernel(const float* __restrict__ P, const float* __restrict__ W) {
    __shared__ float Pt[256 * 33 + 8];
    __shared__ float Wt[4 * 33];
    if (blockIdx.x < 256) {
        float* red = Pt;
        int k = blockIdx.x;
        const float* row = P + k * D;
        float s = 0.f;
        for (int d = threadIdx.x; d < D; d += 256) { float v = row[d]; s += v * v; }
#pragma unroll
        for (int o = 16; o; o >>= 1) s += __shfl_xor_sync(0xffffffffu, s, o);
        if ((threadIdx.x & 31) == 0) red[threadIdx.x >> 5] = s;
        __syncthreads();
        if (threadIdx.x == 0) {
            float t = 0.f;
#pragma unroll
            for (int i = 0; i < 8; ++i) t += red[i];
            red[0] = 1.f / fmaxf(sqrtf(t), 1e-12f);
        }
        __syncthreads();
        float iv = red[0];
        for (int p = threadIdx.x; p < D / 2; p += 256) {
            uint16_t h = packe4m3(row[2 * p] * iv, row[2 * p + 1] * iv);
            *reinterpret_cast<uint16_t*>(g_pn8 + k * D + 2 * p) = h;
        }
    } else {
        int e0 = (blockIdx.x - 256) * 4;
        int k  = threadIdx.x;
        float a0 = 0.f, a1 = 0.f, a2 = 0.f, a3 = 0.f;
        for (int dc = 0; dc < D; dc += 32) {
#pragma unroll
            for (int it = 0; it < 32; ++it) {
                int idx = threadIdx.x + 256 * it;
                int row = idx >> 5, d = idx & 31;
                Pt[row * 33 + d] = P[row * D + dc + d];
            }
            if (threadIdx.x < 128) {
                int e = threadIdx.x >> 5, d = threadIdx.x & 31;
                Wt[e * 33 + d] = W[(e0 + e) * D + dc + d];
            }
            __syncthreads();
#pragma unroll
            for (int d = 0; d < 32; ++d) {
                float p = Pt[k * 33 + d];
                a0 += p * Wt[0 * 33 + d];
                a1 += p * Wt[1 * 33 + d];
                a2 += p * Wt[2 * 33 + d];
                a3 += p * Wt[3 * 33 + d];
            }
            __syncthreads();
        }
        // PW e4m3 scaled x64 (sigma(PW)=1, max ~5 -> x64 well inside 448)
        g_pwt8[(e0 + 0) * KP + k] = (uint8_t)(packe4m3(a0 * 64.f, 0.f) & 0xff);
        g_pwt8[(e0 + 1) * KP + k] = (uint8_t)(packe4m3(a1 * 64.f, 0.f) & 0xff);
        g_pwt8[(e0 + 2) * KP + k] = (uint8_t)(packe4m3(a2 * 64.f, 0.f) & 0xff);
        g_pwt8[(e0 + 3) * KP + k] = (uint8_t)(packe4m3(a3 * 64.f, 0.f) & 0xff);
        // exact column sums C[e0..e0+3] (fp32 reduction over the 256 k-threads)
        float v[4] = {a0, a1, a2, a3};
#pragma unroll
        for (int i = 0; i < 4; ++i) {
            float s = v[i];
#pragma unroll
            for (int o = 16; o; o >>= 1) s += __shfl_xor_sync(0xffffffffu, s, o);
            if ((threadIdx.x & 31) == 0) Pt[i * 8 + (threadIdx.x >> 5)] = s;
        }
        __syncthreads();
        if (threadIdx.x < 4) {
            float s = 0.f;
#pragma unroll
            for (int ww = 0; ww < 8; ++ww) s += Pt[threadIdx.x * 8 + ww];
            g_pwC[e0 + threadIdx.x] = s;
        }
    }
}

// ---------------------------------------------------------------------------
// Main fused kernel: M_TILE=64, 256 threads, 2 CTAs/SM, FP8 GEMM1 + FP8 GEMM2(d-decomp)
// ---------------------------------------------------------------------------
#define OFF_INV   0            // float[64]
#define OFF_INVS  256          // float[64]
#define OFF_PARTS 512          // float[4][64]
#define OFF_EXP   1536         // e4m3 d-tile [64][272B]  = 17408
#define OFF_PW0   18944        // e4m3 [128][272B] = 34816
#define OFF_PW1   53760        // e4m3 [128][272B] = 34816
#define SMEM_MAIN 88576
// phase-1 overlays (e4m3, stride 80B):
#define OFF_XB0   1536                 // e4m3 [64][80]  = 5120
#define OFF_XB1   (1536 + 5120)
#define OFF_PN0   (1536 + 10240)       // e4m3 [256][80] = 20480
#define OFF_PN1   (1536 + 30720)       // ends 52736 < 88576

__global__ __launch_bounds__(256, 2)
void main_kernel(const float* __restrict__ x, const float* __restrict__ bias,
                 float* __restrict__ out) {
    extern __shared__ char smem[];
    const uint32_t sb = smem_u32(smem);
    const int tid = threadIdx.x, w = tid >> 5, lane = tid & 31;
    const int g = lane >> 2, q = lane & 3;
    const long m0 = (long)blockIdx.x * 64;

    float* inv   = reinterpret_cast<float*>(smem + OFF_INV);
    float* invS  = reinterpret_cast<float*>(smem + OFF_INVS);
    float* parts = reinterpret_cast<float*>(smem + OFF_PARTS);

    // ---- phase-1 tiling: wm1 = M half (32 rows), wn1 = N group (64 cols) ----
    const int wm1 = w & 1, wn1 = w >> 1;
    const int xr0 = tid >> 4, xc4 = tid & 15;
    const float* xbase = x + (m0 + xr0) * D + xc4 * 4;
    const uint32_t aoff1 = (wm1 * 32 + (lane & 7) + ((lane >> 3) & 1) * 8) * 80 + ((lane >> 4) & 1) * 16;
    const uint32_t boff1 = (wn1 * 64 + (lane & 7) + ((lane >> 4) & 1) * 8) * 80 + ((lane >> 3) & 1) * 16;

    float acc[2][8][4];
#pragma unroll
    for (int mt = 0; mt < 2; ++mt)
#pragma unroll
        for (int nt = 0; nt < 8; ++nt)
#pragma unroll
            for (int j = 0; j < 4; ++j) acc[mt][nt][j] = 0.f;

    float sq[4] = {0.f, 0.f, 0.f, 0.f};

    // ---- prologue: prefetch x chunk 0, cp.async pn chunk 0 ----
    float4 R[4];
#pragma unroll
    for (int f = 0; f < 4; ++f)
        R[f] = *reinterpret_cast<const float4*>(xbase + f * 16 * D);
#pragma unroll
    for (int it = 0; it < 4; ++it) {
        int idx = tid + 256 * it;          // 0..1023
        int row = idx >> 2, u = idx & 3;   // 256 rows x 4 16B units
        CP16(sb + OFF_PN0 + row * 80 + u * 16, g_pn8 + row * D + u * 16);
    }
    CP_COMMIT();

    // ---- Phase 1 (FP8): sim[64][256] = x @ pn^T (12 K-chunks of 64) ----
    for (int c = 0; c < 12; ++c) {
        const int b = c & 1;
        const uint32_t XB = b ? (sb + OFF_XB1) : (sb + OFF_XB0);
        const uint32_t PN = b ? (sb + OFF_PN1) : (sb + OFF_PN0);
        // convert prefetched x -> e4m3 smem, accumulate sumsq
#pragma unroll
        for (int f = 0; f < 4; ++f) {
            float4 v = R[f];
            sq[f] += v.x * v.x + v.y * v.y + v.z * v.z + v.w * v.w;
            uint32_t word = (uint32_t)packe4m3(v.x, v.y) |
                            ((uint32_t)packe4m3(v.z, v.w) << 16);
            *reinterpret_cast<uint32_t*>(smem + (XB - sb) + (xr0 + 16 * f) * 80 + xc4 * 4) = word;
        }
        // hoisted x prefetch for c+1: latency spans wait+sync+MMA
        if (c < 11) {
#pragma unroll
            for (int f = 0; f < 4; ++f)
                R[f] = *reinterpret_cast<const float4*>(xbase + f * 16 * D + (c + 1) * 64);
        }
        if (c == 11) {
#pragma unroll
            for (int f = 0; f < 4; ++f) {
                float s = sq[f];
                s += __shfl_xor_sync(0xffffffffu, s, 1);
                s += __shfl_xor_sync(0xffffffffu, s, 2);
                s += __shfl_xor_sync(0xffffffffu, s, 4);
                s += __shfl_xor_sync(0xffffffffu, s, 8);
                if ((tid & 15) == 0) inv[xr0 + 16 * f] = 1.f / fmaxf(sqrtf(s), 1e-12f);
            }
        }
        CP_WAIT0();
        __syncthreads();
        if (c < 11) {
            const uint32_t PNn = b ? (sb + OFF_PN0) : (sb + OFF_PN1);
#pragma unroll
            for (int it = 0; it < 4; ++it) {
                int idx = tid + 256 * it;
                int row = idx >> 2, u = idx & 3;
                CP16(PNn + row * 80 + u * 16, g_pn8 + row * D + (c + 1) * 64 + u * 16);
            }
            CP_COMMIT();
        }
#pragma unroll
        for (int ks = 0; ks < 2; ++ks) {
            uint32_t a0[2], a1[2], a2[2], a3[2];
#pragma unroll
            for (int mt = 0; mt < 2; ++mt)
                ldsm_x4(a0[mt], a1[mt], a2[mt], a3[mt], XB + aoff1 + mt * 16 * 80 + ks * 32);
#pragma unroll
            for (int p = 0; p < 4; ++p) {
                uint32_t b0, b1, b2, b3;
                ldsm_x4(b0, b1, b2, b3, PN + boff1 + p * 16 * 80 + ks * 32);
#pragma unroll
                for (int mt = 0; mt < 2; ++mt) {
                    mma8(acc[mt][2 * p],     a0[mt], a1[mt], a2[mt], a3[mt], b0, b1);
                    mma8(acc[mt][2 * p + 1], a0[mt], a1[mt], a2[mt], a3[mt], b2, b3);
                }
            }
        }
    }
    __syncthreads();   // all phase-1 reads done before overlay reuse

    // ---- kick off PW chunk 0 staging (overlaps softmax) ----
#pragma unroll
    for (int it = 0; it < 8; ++it) {
        int idx = tid + 256 * it;           // 0..2047 16B units
        int row = idx >> 4, u = idx & 15;   // 128 rows x 16 units (256 e4m3)
        CP16(sb + OFF_PW0 + row * 272 + u * 16, g_pwt8 + row * KP + u * 16);
    }
    CP_COMMIT();

    // ---- softmax: e = exp(sim/||x||); store d = 64*(e-1) as e4m3; sum e ----
#pragma unroll
    for (int mt = 0; mt < 2; ++mt) {
        const int r0 = wm1 * 32 + mt * 16 + g, r1 = r0 + 8;
        const float iv0 = inv[r0], iv1 = inv[r1];
        float s0 = 0.f, s1 = 0.f;
#pragma unroll
        for (int nt = 0; nt < 8; ++nt) {
            float e0 = __expf(acc[mt][nt][0] * iv0);
            float e1 = __expf(acc[mt][nt][1] * iv0);
            float e2 = __expf(acc[mt][nt][2] * iv1);
            float e3 = __expf(acc[mt][nt][3] * iv1);
            const uint32_t cb = wn1 * 64 + nt * 8 + 2 * q;   // byte col
            *reinterpret_cast<uint16_t*>(smem + OFF_EXP + r0 * 272 + cb) =
                packe4m3(64.f * (e0 - 1.f), 64.f * (e1 - 1.f));
            *reinterpret_cast<uint16_t*>(smem + OFF_EXP + r1 * 272 + cb) =
                packe4m3(64.f * (e2 - 1.f), 64.f * (e3 - 1.f));
            s0 += e0 + e1; s1 += e2 + e3;
        }
        s0 += __shfl_xor_sync(0xffffffffu, s0, 1);
        s0 += __shfl_xor_sync(0xffffffffu, s0, 2);
        s1 += __shfl_xor_sync(0xffffffffu, s1, 1);
        s1 += __shfl_xor_sync(0xffffffffu, s1, 2);
        if (q == 0) { parts[wn1 * 64 + r0] = s0; parts[wn1 * 64 + r1] = s1; }
    }
    __syncthreads();
    if (tid < 64) {
        float s = parts[tid] + parts[64 + tid] + parts[128 + tid] + parts[192 + tid];
        invS[tid] = 1.f / (256.f * s);       // out = (C + corr) / (256*s) + bias
    }

    // ---- Phase 3 (FP8 d-decomp): 6 e-chunks of 128, PW double-buffered ----
    const int wm3 = w & 1, wn3 = w >> 1;      // 2 M groups x 4 N groups (32x32/warp)
    const uint32_t aoff3 = (wm3 * 32 + (lane & 7) + ((lane >> 3) & 1) * 8) * 272 + ((lane >> 4) & 1) * 16;
    const uint32_t boff3 = (wn3 * 32 + (lane & 7) + ((lane >> 4) & 1) * 8) * 272 + ((lane >> 3) & 1) * 16;
    const float inv4096 = 1.f / 4096.f;       // undo (x64 d) * (x64 PW)

    for (int j = 0; j < 6; ++j) {
        const uint32_t PW = (j & 1) ? (sb + OFF_PW1) : (sb + OFF_PW0);
        CP_WAIT0();
        __syncthreads();                      // PW(j) ready; buffer j^1 free; invS visible
        if (j < 5) {                          // load j+1 into other buffer: overlaps MMA+epilogue
            const uint32_t PWn = (j & 1) ? (sb + OFF_PW0) : (sb + OFF_PW1);
#pragma unroll
            for (int it = 0; it < 8; ++it) {
                int idx = tid + 256 * it;
                int row = idx >> 4, u = idx & 15;
                CP16(PWn + row * 272 + u * 16, g_pwt8 + ((j + 1) * 128 + row) * KP + u * 16);
            }
            CP_COMMIT();
        }
        float acc2[2][4][4];
#pragma unroll
        for (int mt = 0; mt < 2; ++mt)
#pragma unroll
            for (int nt = 0; nt < 4; ++nt)
#pragma unroll
                for (int jj = 0; jj < 4; ++jj) acc2[mt][nt][jj] = 0.f;

#pragma unroll
        for (int ks = 0; ks < 8; ++ks) {      // 8 k32-steps over K=256
            uint32_t b0, b1, b2, b3, b4, b5, b6, b7;
            ldsm_x4(b0, b1, b2, b3, PW + boff3 + ks * 32);
            ldsm_x4(b4, b5, b6, b7, PW + boff3 + 16 * 272 + ks * 32);
#pragma unroll
            for (int mt = 0; mt < 2; ++mt) {
                uint32_t a0, a1, a2, a3;
                ldsm_x4(a0, a1, a2, a3, sb + OFF_EXP + aoff3 + mt * 16 * 272 + ks * 32);
                mma8(acc2[mt][0], a0, a1, a2, a3, b0, b1);
                mma8(acc2[mt][1], a0, a1, a2, a3, b2, b3);
                mma8(acc2[mt][2], a0, a1, a2, a3, b4, b5);
                mma8(acc2[mt][3], a0, a1, a2, a3, b6, b7);
            }
        }
        // epilogue: out = (C + corr/4096) * invS + bias
#pragma unroll
        for (int mt = 0; mt < 2; ++mt) {
            const int r0 = wm3 * 32 + mt * 16 + g, r1 = r0 + 8;
            const float is0 = invS[r0], is1 = invS[r1];
#pragma unroll
            for (int nt = 0; nt < 4; ++nt) {
                const int cc = j * 128 + wn3 * 32 + nt * 8 + 2 * q;
                const float2 bv = *reinterpret_cast<const float2*>(bias + cc);
                const float2 Cv = *reinterpret_cast<const float2*>(g_pwC + cc);
                *reinterpret_cast<float2*>(out + (m0 + r0) * D + cc) = make_float2(
                    (Cv.x + acc2[mt][nt][0] * inv4096) * is0 + bv.x,
                    (Cv.y + acc2[mt][nt][1] * inv4096) * is0 + bv.y);
                *reinterpret_cast<float2*>(out + (m0 + r1) * D + cc) = make_float2(
                    (Cv.x + acc2[mt][nt][2] * inv4096) * is1 + bv.x,
                    (Cv.y + acc2[mt][nt][3] * inv4096) * is1 + bv.y);
            }
        }
    }
}

// ---------------------------------------------------------------------------
extern "C" void kernel_launch(void* const* d_in, const int* in_sizes, int n_in,
                              void* d_out, int out_size) {
    const float* x = (const float*)d_in[0];
    const float* P = (const float*)d_in[1];
    const float* W = (const float*)d_in[2];
    const float* b = (const float*)d_in[3];
    float* out = (float*)d_out;

    cudaFuncSetAttribute(main_kernel, cudaFuncAttributeMaxDynamicSharedMemorySize, SMEM_MAIN);

    prep_kernel<<<448, 256>>>(P, W);

    int rows = in_sizes[0] / D;               // 131072
    main_kernel<<<rows / 64, 256, SMEM_MAIN>>>(x, b, out);
}

// round 12
// speedup vs baseline: 1.5306x; 1.5306x over previous
#include <cuda_runtime.h>
#include <cuda_bf16.h>
#include <cstdint>

#define D  768
#define KP 256

__device__ __align__(16) uint8_t       g_pn8[KP * D];   // normalized prototypes e4m3 [k][d]
__device__ __align__(16) __nv_bfloat16 g_pwt[D * KP];   // (P @ W^T / 256) : [e][k] bf16

// ---------------------------------------------------------------------------
__device__ __forceinline__ uint32_t smem_u32(const void* p) {
    uint32_t a;
    asm("{ .reg .u64 t; cvta.to.shared.u64 t, %1; cvt.u32.u64 %0, t; }" : "=r"(a) : "l"(p));
    return a;
}
__device__ __forceinline__ uint32_t packbf(float lo, float hi) {
    __nv_bfloat162 h = __float22bfloat162_rn(make_float2(lo, hi));
    return *reinterpret_cast<uint32_t*>(&h);
}
__device__ __forceinline__ uint16_t packe4m3(float lo, float hi) {
    uint16_t h;
    asm("cvt.rn.satfinite.e4m3x2.f32 %0, %1, %2;" : "=h"(h) : "f"(hi), "f"(lo));
    return h;
}
__device__ __forceinline__ void ldsm_x4(uint32_t& r0, uint32_t& r1, uint32_t& r2, uint32_t& r3,
                                        uint32_t addr) {
    asm volatile("ldmatrix.sync.aligned.m8n8.x4.shared.b16 {%0,%1,%2,%3}, [%4];"
                 : "=r"(r0), "=r"(r1), "=r"(r2), "=r"(r3) : "r"(addr));
}
__device__ __forceinline__ void mma4(float* c, uint32_t a0, uint32_t a1, uint32_t a2, uint32_t a3,
                                     uint32_t b0, uint32_t b1) {
    asm volatile(
        "mma.sync.aligned.m16n8k16.row.col.f32.bf16.bf16.f32 "
        "{%0,%1,%2,%3}, {%4,%5,%6,%7}, {%8,%9}, {%0,%1,%2,%3};"
        : "+f"(c[0]), "+f"(c[1]), "+f"(c[2]), "+f"(c[3])
        : "r"(a0), "r"(a1), "r"(a2), "r"(a3), "r"(b0), "r"(b1));
}
__device__ __forceinline__ void mma8(float* c, uint32_t a0, uint32_t a1, uint32_t a2, uint32_t a3,
                                     uint32_t b0, uint32_t b1) {
    asm volatile(
        "mma.sync.aligned.m16n8k32.row.col.f32.e4m3.e4m3.f32 "
        "{%0,%1,%2,%3}, {%4,%5,%6,%7}, {%8,%9}, {%0,%1,%2,%3};"
        : "+f"(c[0]), "+f"(c[1]), "+f"(c[2]), "+f"(c[3])
        : "r"(a0), "r"(a1), "r"(a2), "r"(a3), "r"(b0), "r"(b1));
}
#define CP16(dst, src) asm volatile("cp.async.cg.shared.global [%0], [%1], 16;" :: "r"(dst), "l"(src))
#define CP_COMMIT()    asm volatile("cp.async.commit_group;" ::: "memory")
#define CP_WAIT0()     asm volatile("cp.async.wait_group 0;" ::: "memory")

// ---------------------------------------------------------------------------
// Prep kernel v2: blocks [0,256) normalize prototypes -> e4m3
//                 blocks [256,304): PWT, 16 e-rows per block (4x less P re-read)
// ---------------------------------------------------------------------------
__global__ void prep_kernel(const float* __restrict__ P, const float* __restrict__ W) {
    __shared__ float Pt[256 * 33 + 8];
    __shared__ float Wt[16 * 33];
    if (blockIdx.x < 256) {
        float* red = Pt;
        int k = blockIdx.x;
        const float* row = P + k * D;
        float s = 0.f;
        for (int d = threadIdx.x; d < D; d += 256) { float v = row[d]; s += v * v; }
#pragma unroll
        for (int o = 16; o; o >>= 1) s += __shfl_xor_sync(0xffffffffu, s, o);
        if ((threadIdx.x & 31) == 0) red[threadIdx.x >> 5] = s;
        __syncthreads();
        if (threadIdx.x == 0) {
            float t = 0.f;
#pragma unroll
            for (int i = 0; i < 8; ++i) t += red[i];
            red[0] = 1.f / fmaxf(sqrtf(t), 1e-12f);
        }
        __syncthreads();
        float iv = red[0];
        for (int p = threadIdx.x; p < D / 2; p += 256) {
            uint16_t h = packe4m3(row[2 * p] * iv, row[2 * p + 1] * iv);
            *reinterpret_cast<uint16_t*>(g_pn8 + k * D + 2 * p) = h;
        }
    } else {
        int e0 = (blockIdx.x - 256) * 16;
        int k  = threadIdx.x;
        float a[16];
#pragma unroll
        for (int i = 0; i < 16; ++i) a[i] = 0.f;
        for (int dc = 0; dc < D; dc += 32) {
#pragma unroll
            for (int it = 0; it < 32; ++it) {
                int idx = threadIdx.x + 256 * it;      // 8192 = 256 rows x 32 cols
                int row = idx >> 5, d = idx & 31;
                Pt[row * 33 + d] = P[row * D + dc + d];
            }
#pragma unroll
            for (int it = 0; it < 2; ++it) {
                int idx = threadIdx.x + 256 * it;      // 512 = 16 rows x 32 cols
                int e = idx >> 5, d = idx & 31;
                Wt[e * 33 + d] = W[(e0 + e) * D + dc + d];
            }
            __syncthreads();
#pragma unroll
            for (int d = 0; d < 32; ++d) {
                float p = Pt[k * 33 + d];
#pragma unroll
                for (int i = 0; i < 16; ++i)
                    a[i] += p * Wt[i * 33 + d];
            }
            __syncthreads();
        }
        const float sc = 1.f / 256.f;
#pragma unroll
        for (int i = 0; i < 16; ++i)
            g_pwt[(e0 + i) * KP + k] = __float2bfloat16(a[i] * sc);
    }
}

// ---------------------------------------------------------------------------
// Main fused kernel (EXACT R8-bench kernel): M_TILE=64, 256 threads, 2 CTAs/SM,
// FP8 GEMM1 + bf16 GEMM2, single-buffer phase 3.
// ---------------------------------------------------------------------------
#define OFF_INV   0            // float[64]
#define OFF_INVS  256          // float[64]
#define OFF_PARTS 512          // float[4][64]
#define OFF_EXP   1536         // bf16 [64][264]  (stride 528B) = 33792
#define OFF_PW    35328        // bf16 [128][264] = 67584
#define SMEM_MAIN 102912
// phase-1 overlays (e4m3 tiles, stride 80B):
#define OFF_XB0   1536                 // e4m3 [64][80]  = 5120
#define OFF_XB1   (1536 + 5120)
#define OFF_PN0   (1536 + 10240)       // e4m3 [256][80] = 20480
#define OFF_PN1   (1536 + 30720)

__global__ __launch_bounds__(256, 2)
void main_kernel(const float* __restrict__ x, const float* __restrict__ bias,
                 float* __restrict__ out) {
    extern __shared__ char smem[];
    const uint32_t sb = smem_u32(smem);
    const int tid = threadIdx.x, w = tid >> 5, lane = tid & 31;
    const int g = lane >> 2, q = lane & 3;
    const long m0 = (long)blockIdx.x * 64;

    float* inv   = reinterpret_cast<float*>(smem + OFF_INV);
    float* invS  = reinterpret_cast<float*>(smem + OFF_INVS);
    float* parts = reinterpret_cast<float*>(smem + OFF_PARTS);

    // ---- phase-1 tiling: wm1 = M half (32 rows), wn1 = N group (64 cols) ----
    const int wm1 = w & 1, wn1 = w >> 1;
    const int xr0 = tid >> 4, xc4 = tid & 15;
    const float* xbase = x + (m0 + xr0) * D + xc4 * 4;
    const uint32_t aoff1 = (wm1 * 32 + (lane & 7) + ((lane >> 3) & 1) * 8) * 80 + ((lane >> 4) & 1) * 16;
    const uint32_t boff1 = (wn1 * 64 + (lane & 7) + ((lane >> 4) & 1) * 8) * 80 + ((lane >> 3) & 1) * 16;

    float acc[2][8][4];
#pragma unroll
    for (int mt = 0; mt < 2; ++mt)
#pragma unroll
        for (int nt = 0; nt < 8; ++nt)
#pragma unroll
            for (int j = 0; j < 4; ++j) acc[mt][nt][j] = 0.f;

    float sq[4] = {0.f, 0.f, 0.f, 0.f};

    // ---- prologue: prefetch x chunk 0, cp.async pn chunk 0 ----
    float4 R[4];
#pragma unroll
    for (int f = 0; f < 4; ++f)
        R[f] = *reinterpret_cast<const float4*>(xbase + f * 16 * D);
#pragma unroll
    for (int it = 0; it < 4; ++it) {
        int idx = tid + 256 * it;          // 0..1023
        int row = idx >> 2, u = idx & 3;   // 256 rows x 4 16B units
        CP16(sb + OFF_PN0 + row * 80 + u * 16, g_pn8 + row * D + u * 16);
    }
    CP_COMMIT();

    // ---- Phase 1 (FP8): sim[64][256] = x @ pn^T (12 K-chunks of 64) ----
    for (int c = 0; c < 12; ++c) {
        const int b = c & 1;
        const uint32_t XB = b ? (sb + OFF_XB1) : (sb + OFF_XB0);
        const uint32_t PN = b ? (sb + OFF_PN1) : (sb + OFF_PN0);
#pragma unroll
        for (int f = 0; f < 4; ++f) {
            float4 v = R[f];
            sq[f] += v.x * v.x + v.y * v.y + v.z * v.z + v.w * v.w;
            uint32_t word = (uint32_t)packe4m3(v.x, v.y) |
                            ((uint32_t)packe4m3(v.z, v.w) << 16);
            *reinterpret_cast<uint32_t*>(smem + (XB - sb) + (xr0 + 16 * f) * 80 + xc4 * 4) = word;
        }
        if (c == 11) {
#pragma unroll
            for (int f = 0; f < 4; ++f) {
                float s = sq[f];
                s += __shfl_xor_sync(0xffffffffu, s, 1);
                s += __shfl_xor_sync(0xffffffffu, s, 2);
                s += __shfl_xor_sync(0xffffffffu, s, 4);
                s += __shfl_xor_sync(0xffffffffu, s, 8);
                if ((tid & 15) == 0) inv[xr0 + 16 * f] = 1.f / fmaxf(sqrtf(s), 1e-12f);
            }
        }
        CP_WAIT0();
        __syncthreads();
        if (c < 11) {
#pragma unroll
            for (int f = 0; f < 4; ++f)
                R[f] = *reinterpret_cast<const float4*>(xbase + f * 16 * D + (c + 1) * 64);
            const uint32_t PNn = b ? (sb + OFF_PN0) : (sb + OFF_PN1);
#pragma unroll
            for (int it = 0; it < 4; ++it) {
                int idx = tid + 256 * it;
                int row = idx >> 2, u = idx & 3;
                CP16(PNn + row * 80 + u * 16, g_pn8 + row * D + (c + 1) * 64 + u * 16);
            }
            CP_COMMIT();
        }
#pragma unroll
        for (int ks = 0; ks < 2; ++ks) {
            uint32_t a0[2], a1[2], a2[2], a3[2];
#pragma unroll
            for (int mt = 0; mt < 2; ++mt)
                ldsm_x4(a0[mt], a1[mt], a2[mt], a3[mt], XB + aoff1 + mt * 16 * 80 + ks * 32);
#pragma unroll
            for (int p = 0; p < 4; ++p) {
                uint32_t b0, b1, b2, b3;
                ldsm_x4(b0, b1, b2, b3, PN + boff1 + p * 16 * 80 + ks * 32);
#pragma unroll
                for (int mt = 0; mt < 2; ++mt) {
                    mma8(acc[mt][2 * p],     a0[mt], a1[mt], a2[mt], a3[mt], b0, b1);
                    mma8(acc[mt][2 * p + 1], a0[mt], a1[mt], a2[mt], a3[mt], b2, b3);
                }
            }
        }
    }
    __syncthreads();   // all phase-1 reads done before overlay reuse

    // ---- kick off PW chunk 0 staging (overlaps softmax) ----
#pragma unroll
    for (int it = 0; it < 16; ++it) {
        int idx = tid + 256 * it;           // 0..4095 16B units
        int row = idx >> 5, u = idx & 31;   // 128 rows x 32 units
        CP16(sb + OFF_PW + row * 528 + u * 16,
             reinterpret_cast<const char*>(g_pwt) + row * 512 + u * 16);
    }
    CP_COMMIT();

    // ---- softmax: scale by inv[row], exp, write bf16 exp tile + partial sums ----
#pragma unroll
    for (int mt = 0; mt < 2; ++mt) {
        const int r0 = wm1 * 32 + mt * 16 + g, r1 = r0 + 8;
        const float iv0 = inv[r0], iv1 = inv[r1];
        float s0 = 0.f, s1 = 0.f;
#pragma unroll
        for (int nt = 0; nt < 8; ++nt) {
            float e0 = __expf(acc[mt][nt][0] * iv0);
            float e1 = __expf(acc[mt][nt][1] * iv0);
            float e2 = __expf(acc[mt][nt][2] * iv1);
            float e3 = __expf(acc[mt][nt][3] * iv1);
            const uint32_t cb = (wn1 * 64 + nt * 8 + 2 * q) * 2;
            *reinterpret_cast<uint32_t*>(smem + OFF_EXP + r0 * 528 + cb) = packbf(e0, e1);
            *reinterpret_cast<uint32_t*>(smem + OFF_EXP + r1 * 528 + cb) = packbf(e2, e3);
            s0 += e0 + e1; s1 += e2 + e3;
        }
        s0 += __shfl_xor_sync(0xffffffffu, s0, 1);
        s0 += __shfl_xor_sync(0xffffffffu, s0, 2);
        s1 += __shfl_xor_sync(0xffffffffu, s1, 1);
        s1 += __shfl_xor_sync(0xffffffffu, s1, 2);
        if (q == 0) { parts[wn1 * 64 + r0] = s0; parts[wn1 * 64 + r1] = s1; }
    }
    __syncthreads();
    if (tid < 64) {
        float s = parts[tid] + parts[64 + tid] + parts[128 + tid] + parts[192 + tid];
        invS[tid] = 1.f / s;
    }

    // ---- Phase 3 (bf16): out[64][768] = exp @ PWT^T (6 e-chunks of 128) ----
    const int wm3 = w & 1, wn3 = w >> 1;      // 2 M groups x 4 N groups (32x32/warp)
    const uint32_t aoff3 = (wm3 * 32 + (lane & 7) + ((lane >> 3) & 1) * 8) * 528 + ((lane >> 4) & 1) * 16;
    const uint32_t boff3 = (wn3 * 32 + (lane & 7) + ((lane >> 4) & 1) * 8) * 528 + ((lane >> 3) & 1) * 16;

    for (int j = 0; j < 6; ++j) {
        CP_WAIT0();
        __syncthreads();                      // PW chunk j ready (and invS visible at j=0)

        float acc2[2][4][4];
#pragma unroll
        for (int mt = 0; mt < 2; ++mt)
#pragma unroll
            for (int nt = 0; nt < 4; ++nt)
#pragma unroll
                for (int jj = 0; jj < 4; ++jj) acc2[mt][nt][jj] = 0.f;

#pragma unroll
        for (int ks = 0; ks < 16; ++ks) {
            uint32_t b0, b1, b2, b3, b4, b5, b6, b7;
            ldsm_x4(b0, b1, b2, b3, sb + OFF_PW + boff3 + ks * 32);
            ldsm_x4(b4, b5, b6, b7, sb + OFF_PW + boff3 + 16 * 528 + ks * 32);
#pragma unroll
            for (int mt = 0; mt < 2; ++mt) {
                uint32_t a0, a1, a2, a3;
                ldsm_x4(a0, a1, a2, a3, sb + OFF_EXP + aoff3 + mt * 16 * 528 + ks * 32);
                mma4(acc2[mt][0], a0, a1, a2, a3, b0, b1);
                mma4(acc2[mt][1], a0, a1, a2, a3, b2, b3);
                mma4(acc2[mt][2], a0, a1, a2, a3, b4, b5);
                mma4(acc2[mt][3], a0, a1, a2, a3, b6, b7);
            }
        }
        __syncthreads();                      // all PW reads done
        if (j < 5) {
#pragma unroll
            for (int it = 0; it < 16; ++it) {
                int idx = tid + 256 * it;
                int row = idx >> 5, u = idx & 31;
                CP16(sb + OFF_PW + row * 528 + u * 16,
                     reinterpret_cast<const char*>(g_pwt) + ((j + 1) * 128 + row) * 512 + u * 16);
            }
            CP_COMMIT();
        }
        // epilogue (overlaps next PW load): divide by exp-sum, add bias, store
#pragma unroll
        for (int mt = 0; mt < 2; ++mt) {
            const int r0 = wm3 * 32 + mt * 16 + g, r1 = r0 + 8;
            const float is0 = invS[r0], is1 = invS[r1];
#pragma unroll
            for (int nt = 0; nt < 4; ++nt) {
                const int cc = j * 128 + wn3 * 32 + nt * 8 + 2 * q;
                const float2 bv = *reinterpret_cast<const float2*>(bias + cc);
                *reinterpret_cast<float2*>(out + (m0 + r0) * D + cc) =
                    make_float2(acc2[mt][nt][0] * is0 + bv.x, acc2[mt][nt][1] * is0 + bv.y);
                *reinterpret_cast<float2*>(out + (m0 + r1) * D + cc) =
                    make_float2(acc2[mt][nt][2] * is1 + bv.x, acc2[mt][nt][3] * is1 + bv.y);
            }
        }
    }
}

// ---------------------------------------------------------------------------
extern "C" void kernel_launch(void* const* d_in, const int* in_sizes, int n_in,
                              void* d_out, int out_size) {
    const float* x = (const float*)d_in[0];
    const float* P = (const float*)d_in[1];
    const float* W = (const float*)d_in[2];
    const float* b = (const float*)d_in[3];
    float* out = (float*)d_out;

    cudaFuncSetAttribute(main_kernel, cudaFuncAttributeMaxDynamicSharedMemorySize, SMEM_MAIN);

    prep_kernel<<<304, 256>>>(P, W);

    int rows = in_sizes[0] / D;               // 131072
    main_kernel<<<rows / 64, 256, SMEM_MAIN>>>(x, b, out);
}

// round 13
// speedup vs baseline: 1.5457x; 1.0098x over previous
#include <cuda_runtime.h>
#include <cuda_bf16.h>
#include <cstdint>

#define D  768
#define KP 256

__device__ __align__(16) uint8_t g_pn8[KP * D];    // normalized prototypes e4m3 [k][d]
__device__ __align__(16) uint8_t g_pwt8[D * KP];   // e4m3( (P@W^T)[k][e] * 64 ) : [e][k]
__device__ __align__(16) float   g_pwC[D];         // C[e] = sum_k (P@W^T)[k][e]  (exact fp32)

// ---------------------------------------------------------------------------
__device__ __forceinline__ uint32_t smem_u32(const void* p) {
    uint32_t a;
    asm("{ .reg .u64 t; cvta.to.shared.u64 t, %1; cvt.u32.u64 %0, t; }" : "=r"(a) : "l"(p));
    return a;
}
__device__ __forceinline__ uint16_t packe4m3(float lo, float hi) {
    uint16_t h;
    asm("cvt.rn.satfinite.e4m3x2.f32 %0, %1, %2;" : "=h"(h) : "f"(hi), "f"(lo));
    return h;
}
__device__ __forceinline__ void ldsm_x4(uint32_t& r0, uint32_t& r1, uint32_t& r2, uint32_t& r3,
                                        uint32_t addr) {
    asm volatile("ldmatrix.sync.aligned.m8n8.x4.shared.b16 {%0,%1,%2,%3}, [%4];"
                 : "=r"(r0), "=r"(r1), "=r"(r2), "=r"(r3) : "r"(addr));
}
__device__ __forceinline__ void mma8(float* c, uint32_t a0, uint32_t a1, uint32_t a2, uint32_t a3,
                                     uint32_t b0, uint32_t b1) {
    asm volatile(
        "mma.sync.aligned.m16n8k32.row.col.f32.e4m3.e4m3.f32 "
        "{%0,%1,%2,%3}, {%4,%5,%6,%7}, {%8,%9}, {%0,%1,%2,%3};"
        : "+f"(c[0]), "+f"(c[1]), "+f"(c[2]), "+f"(c[3])
        : "r"(a0), "r"(a1), "r"(a2), "r"(a3), "r"(b0), "r"(b1));
}
#define CP16(dst, src) asm volatile("cp.async.cg.shared.global [%0], [%1], 16;" :: "r"(dst), "l"(src))
#define CP_COMMIT()    asm volatile("cp.async.commit_group;" ::: "memory")
#define CP_WAIT0()     asm volatile("cp.async.wait_group 0;" ::: "memory")

// ---------------------------------------------------------------------------
// Prep (R8 448-block shape + C): [0,256) prototypes -> e4m3;
//                                [256,448) PW e4m3 (x64) + exact column-sum C
// ---------------------------------------------------------------------------
__global__ void prep_kernel(const float* __restrict__ P, const float* __restrict__ W) {
    __shared__ float Pt[256 * 33 + 8];
    __shared__ float Wt[4 * 33];
    if (blockIdx.x < 256) {
        float* red = Pt;
        int k = blockIdx.x;
        const float* row = P + k * D;
        float s = 0.f;
        for (int d = threadIdx.x; d < D; d += 256) { float v = row[d]; s += v * v; }
#pragma unroll
        for (int o = 16; o; o >>= 1) s += __shfl_xor_sync(0xffffffffu, s, o);
        if ((threadIdx.x & 31) == 0) red[threadIdx.x >> 5] = s;
        __syncthreads();
        if (threadIdx.x == 0) {
            float t = 0.f;
#pragma unroll
            for (int i = 0; i < 8; ++i) t += red[i];
            red[0] = 1.f / fmaxf(sqrtf(t), 1e-12f);
        }
        __syncthreads();
        float iv = red[0];
        for (int p = threadIdx.x; p < D / 2; p += 256) {
            uint16_t h = packe4m3(row[2 * p] * iv, row[2 * p + 1] * iv);
            *reinterpret_cast<uint16_t*>(g_pn8 + k * D + 2 * p) = h;
        }
    } else {
        int e0 = (blockIdx.x - 256) * 4;
        int k  = threadIdx.x;
        float a0 = 0.f, a1 = 0.f, a2 = 0.f, a3 = 0.f;
        for (int dc = 0; dc < D; dc += 32) {
#pragma unroll
            for (int it = 0; it < 32; ++it) {
                int idx = threadIdx.x + 256 * it;
                int row = idx >> 5, d = idx & 31;
                Pt[row * 33 + d] = P[row * D + dc + d];
            }
            if (threadIdx.x < 128) {
                int e = threadIdx.x >> 5, d = threadIdx.x & 31;
                Wt[e * 33 + d] = W[(e0 + e) * D + dc + d];
            }
            __syncthreads();
#pragma unroll
            for (int d = 0; d < 32; ++d) {
                float p = Pt[k * 33 + d];
                a0 += p * Wt[0 * 33 + d];
                a1 += p * Wt[1 * 33 + d];
                a2 += p * Wt[2 * 33 + d];
                a3 += p * Wt[3 * 33 + d];
            }
            __syncthreads();
        }
        // PW e4m3 scaled x64 (values ~N(0,1); x64 well inside e4m3 max 448)
        g_pwt8[(e0 + 0) * KP + k] = (uint8_t)(packe4m3(a0 * 64.f, 0.f) & 0xff);
        g_pwt8[(e0 + 1) * KP + k] = (uint8_t)(packe4m3(a1 * 64.f, 0.f) & 0xff);
        g_pwt8[(e0 + 2) * KP + k] = (uint8_t)(packe4m3(a2 * 64.f, 0.f) & 0xff);
        g_pwt8[(e0 + 3) * KP + k] = (uint8_t)(packe4m3(a3 * 64.f, 0.f) & 0xff);
        // exact column sums C[e0..e0+3]
        float v[4] = {a0, a1, a2, a3};
#pragma unroll
        for (int i = 0; i < 4; ++i) {
            float s = v[i];
#pragma unroll
            for (int o = 16; o; o >>= 1) s += __shfl_xor_sync(0xffffffffu, s, o);
            if ((threadIdx.x & 31) == 0) Pt[i * 8 + (threadIdx.x >> 5)] = s;
        }
        __syncthreads();
        if (threadIdx.x < 4) {
            float s = 0.f;
#pragma unroll
            for (int ww = 0; ww < 8; ++ww) s += Pt[threadIdx.x * 8 + ww];
            g_pwC[e0 + threadIdx.x] = s;
        }
    }
}

// ---------------------------------------------------------------------------
// Main kernel: EXACT R9 structure (378.8us) + d-decomposition + smem C/bias
// ---------------------------------------------------------------------------
#define OFF_INV   0            // float[64]
#define OFF_INVS  256          // float[64]
#define OFF_PARTS 512          // float[4][64]
#define OFF_EXP   1536         // e4m3 d-tile [64][272B]  = 17408
#define OFF_PW    18944        // e4m3 [128][272B] = 34816 -> ends 53760
#define OFF_C     53760        // float[768] = 3072
#define OFF_B     56832        // float[768] = 3072
#define SMEM_MAIN 59904
// phase-1 overlays (e4m3 tiles, stride 80B):
#define OFF_XB0   1536                 // e4m3 [64][80]  = 5120
#define OFF_XB1   (1536 + 5120)
#define OFF_PN0   (1536 + 10240)       // e4m3 [256][80] = 20480
#define OFF_PN1   (1536 + 30720)       // ends 52736

__global__ __launch_bounds__(256, 2)
void main_kernel(const float* __restrict__ x, const float* __restrict__ bias,
                 float* __restrict__ out) {
    extern __shared__ char smem[];
    const uint32_t sb = smem_u32(smem);
    const int tid = threadIdx.x, w = tid >> 5, lane = tid & 31;
    const int g = lane >> 2, q = lane & 3;
    const long m0 = (long)blockIdx.x * 64;

    float* inv   = reinterpret_cast<float*>(smem + OFF_INV);
    float* invS  = reinterpret_cast<float*>(smem + OFF_INVS);
    float* parts = reinterpret_cast<float*>(smem + OFF_PARTS);
    float* Cs    = reinterpret_cast<float*>(smem + OFF_C);
    float* Bs    = reinterpret_cast<float*>(smem + OFF_B);

    // stage C + bias into smem (hidden under prologue; first use is far later)
#pragma unroll
    for (int i = 0; i < 3; ++i) {
        Cs[tid + 256 * i] = g_pwC[tid + 256 * i];
        Bs[tid + 256 * i] = bias[tid + 256 * i];
    }

    // ---- phase-1 tiling: wm1 = M half (32 rows), wn1 = N group (64 cols) ----
    const int wm1 = w & 1, wn1 = w >> 1;
    const int xr0 = tid >> 4, xc4 = tid & 15;
    const float* xbase = x + (m0 + xr0) * D + xc4 * 4;
    const uint32_t aoff1 = (wm1 * 32 + (lane & 7) + ((lane >> 3) & 1) * 8) * 80 + ((lane >> 4) & 1) * 16;
    const uint32_t boff1 = (wn1 * 64 + (lane & 7) + ((lane >> 4) & 1) * 8) * 80 + ((lane >> 3) & 1) * 16;

    float acc[2][8][4];
#pragma unroll
    for (int mt = 0; mt < 2; ++mt)
#pragma unroll
        for (int nt = 0; nt < 8; ++nt)
#pragma unroll
            for (int j = 0; j < 4; ++j) acc[mt][nt][j] = 0.f;

    float sq[4] = {0.f, 0.f, 0.f, 0.f};

    // ---- prologue: prefetch x chunk 0, cp.async pn chunk 0 ----
    float4 R[4];
#pragma unroll
    for (int f = 0; f < 4; ++f)
        R[f] = *reinterpret_cast<const float4*>(xbase + f * 16 * D);
#pragma unroll
    for (int it = 0; it < 4; ++it) {
        int idx = tid + 256 * it;          // 0..1023
        int row = idx >> 2, u = idx & 3;   // 256 rows x 4 16B units
        CP16(sb + OFF_PN0 + row * 80 + u * 16, g_pn8 + row * D + u * 16);
    }
    CP_COMMIT();

    // ---- Phase 1 (FP8): sim[64][256] = x @ pn^T (12 K-chunks of 64) ----
    for (int c = 0; c < 12; ++c) {
        const int b = c & 1;
        const uint32_t XB = b ? (sb + OFF_XB1) : (sb + OFF_XB0);
        const uint32_t PN = b ? (sb + OFF_PN1) : (sb + OFF_PN0);
#pragma unroll
        for (int f = 0; f < 4; ++f) {
            float4 v = R[f];
            sq[f] += v.x * v.x + v.y * v.y + v.z * v.z + v.w * v.w;
            uint32_t word = (uint32_t)packe4m3(v.x, v.y) |
                            ((uint32_t)packe4m3(v.z, v.w) << 16);
            *reinterpret_cast<uint32_t*>(smem + (XB - sb) + (xr0 + 16 * f) * 80 + xc4 * 4) = word;
        }
        if (c == 11) {
#pragma unroll
            for (int f = 0; f < 4; ++f) {
                float s = sq[f];
                s += __shfl_xor_sync(0xffffffffu, s, 1);
                s += __shfl_xor_sync(0xffffffffu, s, 2);
                s += __shfl_xor_sync(0xffffffffu, s, 4);
                s += __shfl_xor_sync(0xffffffffu, s, 8);
                if ((tid & 15) == 0) inv[xr0 + 16 * f] = 1.f / fmaxf(sqrtf(s), 1e-12f);
            }
        }
        CP_WAIT0();
        __syncthreads();
        if (c < 11) {
#pragma unroll
            for (int f = 0; f < 4; ++f)
                R[f] = *reinterpret_cast<const float4*>(xbase + f * 16 * D + (c + 1) * 64);
            const uint32_t PNn = b ? (sb + OFF_PN0) : (sb + OFF_PN1);
#pragma unroll
            for (int it = 0; it < 4; ++it) {
                int idx = tid + 256 * it;
                int row = idx >> 2, u = idx & 3;
                CP16(PNn + row * 80 + u * 16, g_pn8 + row * D + (c + 1) * 64 + u * 16);
            }
            CP_COMMIT();
        }
#pragma unroll
        for (int ks = 0; ks < 2; ++ks) {
            uint32_t a0[2], a1[2], a2[2], a3[2];
#pragma unroll
            for (int mt = 0; mt < 2; ++mt)
                ldsm_x4(a0[mt], a1[mt], a2[mt], a3[mt], XB + aoff1 + mt * 16 * 80 + ks * 32);
#pragma unroll
            for (int p = 0; p < 4; ++p) {
                uint32_t b0, b1, b2, b3;
                ldsm_x4(b0, b1, b2, b3, PN + boff1 + p * 16 * 80 + ks * 32);
#pragma unroll
                for (int mt = 0; mt < 2; ++mt) {
                    mma8(acc[mt][2 * p],     a0[mt], a1[mt], a2[mt], a3[mt], b0, b1);
                    mma8(acc[mt][2 * p + 1], a0[mt], a1[mt], a2[mt], a3[mt], b2, b3);
                }
            }
        }
    }
    __syncthreads();   // all phase-1 reads done before overlay reuse

    // ---- kick off PW chunk 0 staging (overlaps softmax) ----
#pragma unroll
    for (int it = 0; it < 8; ++it) {
        int idx = tid + 256 * it;           // 0..2047 16B units
        int row = idx >> 4, u = idx & 15;   // 128 rows x 16 units (256 e4m3)
        CP16(sb + OFF_PW + row * 272 + u * 16, g_pwt8 + row * KP + u * 16);
    }
    CP_COMMIT();

    // ---- softmax: e = exp(sim/||x||); store d = 64*(e-1) as e4m3; sum e ----
#pragma unroll
    for (int mt = 0; mt < 2; ++mt) {
        const int r0 = wm1 * 32 + mt * 16 + g, r1 = r0 + 8;
        const float iv0 = inv[r0], iv1 = inv[r1];
        float s0 = 0.f, s1 = 0.f;
#pragma unroll
        for (int nt = 0; nt < 8; ++nt) {
            float e0 = __expf(acc[mt][nt][0] * iv0);
            float e1 = __expf(acc[mt][nt][1] * iv0);
            float e2 = __expf(acc[mt][nt][2] * iv1);
            float e3 = __expf(acc[mt][nt][3] * iv1);
            const uint32_t cb = wn1 * 64 + nt * 8 + 2 * q;   // byte col
            *reinterpret_cast<uint16_t*>(smem + OFF_EXP + r0 * 272 + cb) =
                packe4m3(64.f * (e0 - 1.f), 64.f * (e1 - 1.f));
            *reinterpret_cast<uint16_t*>(smem + OFF_EXP + r1 * 272 + cb) =
                packe4m3(64.f * (e2 - 1.f), 64.f * (e3 - 1.f));
            s0 += e0 + e1; s1 += e2 + e3;
        }
        s0 += __shfl_xor_sync(0xffffffffu, s0, 1);
        s0 += __shfl_xor_sync(0xffffffffu, s0, 2);
        s1 += __shfl_xor_sync(0xffffffffu, s1, 1);
        s1 += __shfl_xor_sync(0xffffffffu, s1, 2);
        if (q == 0) { parts[wn1 * 64 + r0] = s0; parts[wn1 * 64 + r1] = s1; }
    }
    __syncthreads();
    if (tid < 64) {
        float s = parts[tid] + parts[64 + tid] + parts[128 + tid] + parts[192 + tid];
        invS[tid] = 1.f / (256.f * s);       // out = (C + corr) / (256*s) + bias
    }

    // ---- Phase 3 (FP8 d-decomp): 6 e-chunks of 128, single PW buffer ----
    const int wm3 = w & 1, wn3 = w >> 1;      // 2 M groups x 4 N groups (32x32/warp)
    const uint32_t aoff3 = (wm3 * 32 + (lane & 7) + ((lane >> 3) & 1) * 8) * 272 + ((lane >> 4) & 1) * 16;
    const uint32_t boff3 = (wn3 * 32 + (lane & 7) + ((lane >> 4) & 1) * 8) * 272 + ((lane >> 3) & 1) * 16;
    const float inv4096 = 1.f / 4096.f;       // undo (x64 d) * (x64 PW)

    for (int j = 0; j < 6; ++j) {
        CP_WAIT0();
        __syncthreads();                      // PW chunk j ready (and invS visible at j=0)

        float acc2[2][4][4];
#pragma unroll
        for (int mt = 0; mt < 2; ++mt)
#pragma unroll
            for (int nt = 0; nt < 4; ++nt)
#pragma unroll
                for (int jj = 0; jj < 4; ++jj) acc2[mt][nt][jj] = 0.f;

#pragma unroll
        for (int ks = 0; ks < 8; ++ks) {      // 8 k32-steps over K=256
            uint32_t b0, b1, b2, b3, b4, b5, b6, b7;
            ldsm_x4(b0, b1, b2, b3, sb + OFF_PW + boff3 + ks * 32);
            ldsm_x4(b4, b5, b6, b7, sb + OFF_PW + boff3 + 16 * 272 + ks * 32);
#pragma unroll
            for (int mt = 0; mt < 2; ++mt) {
                uint32_t a0, a1, a2, a3;
                ldsm_x4(a0, a1, a2, a3, sb + OFF_EXP + aoff3 + mt * 16 * 272 + ks * 32);
                mma8(acc2[mt][0], a0, a1, a2, a3, b0, b1);
                mma8(acc2[mt][1], a0, a1, a2, a3, b2, b3);
                mma8(acc2[mt][2], a0, a1, a2, a3, b4, b5);
                mma8(acc2[mt][3], a0, a1, a2, a3, b6, b7);
            }
        }
        __syncthreads();                      // all PW reads done
        if (j < 5) {
#pragma unroll
            for (int it = 0; it < 8; ++it) {
                int idx = tid + 256 * it;
                int row = idx >> 4, u = idx & 15;
                CP16(sb + OFF_PW + row * 272 + u * 16,
                     g_pwt8 + ((j + 1) * 128 + row) * KP + u * 16);
            }
            CP_COMMIT();
        }
        // epilogue: out = (C + corr/4096) * invS + bias  (C, bias from smem)
#pragma unroll
        for (int mt = 0; mt < 2; ++mt) {
            const int r0 = wm3 * 32 + mt * 16 + g, r1 = r0 + 8;
            const float is0 = invS[r0], is1 = invS[r1];
#pragma unroll
            for (int nt = 0; nt < 4; ++nt) {
                const int cc = j * 128 + wn3 * 32 + nt * 8 + 2 * q;
                const float2 bv = *reinterpret_cast<const float2*>(Bs + cc);
                const float2 Cv = *reinterpret_cast<const float2*>(Cs + cc);
                *reinterpret_cast<float2*>(out + (m0 + r0) * D + cc) = make_float2(
                    (Cv.x + acc2[mt][nt][0] * inv4096) * is0 + bv.x,
                    (Cv.y + acc2[mt][nt][1] * inv4096) * is0 + bv.y);
                *reinterpret_cast<float2*>(out + (m0 + r1) * D + cc) = make_float2(
                    (Cv.x + acc2[mt][nt][2] * inv4096) * is1 + bv.x,
                    (Cv.y + acc2[mt][nt][3] * inv4096) * is1 + bv.y);
            }
        }
    }
}

// ---------------------------------------------------------------------------
extern "C" void kernel_launch(void* const* d_in, const int* in_sizes, int n_in,
                              void* d_out, int out_size) {
    const float* x = (const float*)d_in[0];
    const float* P = (const float*)d_in[1];
    const float* W = (const float*)d_in[2];
    const float* b = (const float*)d_in[3];
    float* out = (float*)d_out;

    cudaFuncSetAttribute(main_kernel, cudaFuncAttributeMaxDynamicSharedMemorySize, SMEM_MAIN);

    prep_kernel<<<448, 256>>>(P, W);

    int rows = in_sizes[0] / D;               // 131072
    main_kernel<<<rows / 64, 256, SMEM_MAIN>>>(x, b, out);
}

// round 16
// speedup vs baseline: 1.5957x; 1.0324x over previous
#include <cuda_runtime.h>
#include <cuda_bf16.h>
#include <cstdint>

#define D  768
#define KP 256

__device__ __align__(16) uint8_t g_pn8[KP * D];    // normalized prototypes e4m3 [k][d]
__device__ __align__(16) uint8_t g_pwt8[D * KP];   // e4m3( (P@W^T)[k][e] * 64 ) : [e][k]
__device__ __align__(16) float   g_pwCp[4 * D];    // C partials per k-group (summed in main)

// ---------------------------------------------------------------------------
__device__ __forceinline__ uint32_t smem_u32(const void* p) {
    uint32_t a;
    asm("{ .reg .u64 t; cvta.to.shared.u64 t, %1; cvt.u32.u64 %0, t; }" : "=r"(a) : "l"(p));
    return a;
}
__device__ __forceinline__ uint16_t packe4m3(float lo, float hi) {
    uint16_t h;
    asm("cvt.rn.satfinite.e4m3x2.f32 %0, %1, %2;" : "=h"(h) : "f"(hi), "f"(lo));
    return h;
}
__device__ __forceinline__ void ldsm_x4(uint32_t& r0, uint32_t& r1, uint32_t& r2, uint32_t& r3,
                                        uint32_t addr) {
    asm volatile("ldmatrix.sync.aligned.m8n8.x4.shared.b16 {%0,%1,%2,%3}, [%4];"
                 : "=r"(r0), "=r"(r1), "=r"(r2), "=r"(r3) : "r"(addr));
}
__device__ __forceinline__ void mma8(float* c, uint32_t a0, uint32_t a1, uint32_t a2, uint32_t a3,
                                     uint32_t b0, uint32_t b1) {
    asm volatile(
        "mma.sync.aligned.m16n8k32.row.col.f32.e4m3.e4m3.f32 "
        "{%0,%1,%2,%3}, {%4,%5,%6,%7}, {%8,%9}, {%0,%1,%2,%3};"
        : "+f"(c[0]), "+f"(c[1]), "+f"(c[2]), "+f"(c[3])
        : "r"(a0), "r"(a1), "r"(a2), "r"(a3), "r"(b0), "r"(b1));
}
#define CP16(dst, src) asm volatile("cp.async.cg.shared.global [%0], [%1], 16;" :: "r"(dst), "l"(src))
#define CP_COMMIT()    asm volatile("cp.async.commit_group;" ::: "memory")
#define CP_WAIT0()     asm volatile("cp.async.wait_group 0;" ::: "memory")

// ---------------------------------------------------------------------------
// Prep v3: [0,256) prototypes -> e4m3
//          [256,448): PWT e4m3(x64), grid = 48 e-groups x 4 k-groups
//                     (each block reads only 64 P rows -> 4x less traffic)
// ---------------------------------------------------------------------------
__global__ void prep_kernel(const float* __restrict__ P, const float* __restrict__ W) {
    __shared__ float Pt[64 * 33];
    __shared__ float Wt[16 * 33 + 8];
    __shared__ float Rd[8][4];
    const int tid = threadIdx.x;
    if (blockIdx.x < 256) {
        float* red = Pt;
        int k = blockIdx.x;
        const float* row = P + k * D;
        float s = 0.f;
        for (int d = tid; d < D; d += 256) { float v = row[d]; s += v * v; }
#pragma unroll
        for (int o = 16; o; o >>= 1) s += __shfl_xor_sync(0xffffffffu, s, o);
        if ((tid & 31) == 0) red[tid >> 5] = s;
        __syncthreads();
        if (tid == 0) {
            float t = 0.f;
#pragma unroll
            for (int i = 0; i < 8; ++i) t += red[i];
            red[0] = 1.f / fmaxf(sqrtf(t), 1e-12f);
        }
        __syncthreads();
        float iv = red[0];
        for (int p = tid; p < D / 2; p += 256) {
            uint16_t h = packe4m3(row[2 * p] * iv, row[2 * p + 1] * iv);
            *reinterpret_cast<uint16_t*>(g_pn8 + k * D + 2 * p) = h;
        }
    } else {
        const int bid = blockIdx.x - 256;           // 0..191
        const int eg = bid >> 2, kg = bid & 3;
        const int e0 = eg * 16, k0 = kg * 64;
        const int kk = tid & 63, esub = tid >> 6;   // 4 e's per thread
        float a[4] = {0.f, 0.f, 0.f, 0.f};
        for (int dc = 0; dc < D; dc += 32) {
#pragma unroll
            for (int it = 0; it < 8; ++it) {        // P tile 64x32
                int idx = tid + 256 * it;
                int row = idx >> 5, d = idx & 31;
                Pt[row * 33 + d] = P[(k0 + row) * D + dc + d];
            }
#pragma unroll
            for (int it = 0; it < 2; ++it) {        // W tile 16x32
                int idx = tid + 256 * it;
                int e = idx >> 5, d = idx & 31;
                Wt[e * 33 + d] = W[(e0 + e) * D + dc + d];
            }
            __syncthreads();
#pragma unroll
            for (int d = 0; d < 32; ++d) {
                float p = Pt[kk * 33 + d];
                a[0] += p * Wt[(esub * 4 + 0) * 33 + d];
                a[1] += p * Wt[(esub * 4 + 1) * 33 + d];
                a[2] += p * Wt[(esub * 4 + 2) * 33 + d];
                a[3] += p * Wt[(esub * 4 + 3) * 33 + d];
            }
            __syncthreads();
        }
#pragma unroll
        for (int i = 0; i < 4; ++i)
            g_pwt8[(e0 + esub * 4 + i) * KP + (k0 + kk)] =
                (uint8_t)(packe4m3(a[i] * 64.f, 0.f) & 0xff);
        // C partials over this k-group (reduce across the 64 kk threads)
        const int w = tid >> 5;
#pragma unroll
        for (int i = 0; i < 4; ++i) {
            float s = a[i];
#pragma unroll
            for (int o = 16; o; o >>= 1) s += __shfl_xor_sync(0xffffffffu, s, o);
            if ((tid & 31) == 0) Rd[w][i] = s;
        }
        __syncthreads();
        if (tid < 16) {
            int es = tid >> 2, i = tid & 3;
            g_pwCp[kg * D + e0 + es * 4 + i] = Rd[es * 2][i] + Rd[es * 2 + 1][i];
        }
    }
}

// ---------------------------------------------------------------------------
// Main kernel: R13 math (d-decomp, rel_err 5.1e-5) + bubble-filling schedule
// ---------------------------------------------------------------------------
#define OFF_INV   0            // float[64]
#define OFF_INVS  256          // float[64]
#define OFF_PARTS 512          // float[4][64]
#define OFF_EXP   1536         // e4m3 d-tile [64][272B]  = 17408
#define OFF_PW0   18944        // e4m3 [128][272B] = 34816
#define OFF_PW1   53760        // e4m3 [128][272B] = 34816
#define OFF_C     88576        // float[768]
#define OFF_B     91648        // float[768]
#define SMEM_MAIN 94720
// phase-1 overlays (e4m3 tiles, stride 80B):
#define OFF_XB0   1536                 // e4m3 [64][80]  = 5120
#define OFF_XB1   (1536 + 5120)
#define OFF_PN0   (1536 + 10240)       // e4m3 [256][80] = 20480
#define OFF_PN1   (1536 + 30720)       // ends 52736

__global__ __launch_bounds__(256, 2)
void main_kernel(const float* __restrict__ x, const float* __restrict__ bias,
                 float* __restrict__ out) {
    extern __shared__ char smem[];
    const uint32_t sb = smem_u32(smem);
    const int tid = threadIdx.x, w = tid >> 5, lane = tid & 31;
    const int g = lane >> 2, q = lane & 3;
    const long m0 = (long)blockIdx.x * 64;

    float* inv   = reinterpret_cast<float*>(smem + OFF_INV);
    float* invS  = reinterpret_cast<float*>(smem + OFF_INVS);
    float* parts = reinterpret_cast<float*>(smem + OFF_PARTS);
    float* Cs    = reinterpret_cast<float*>(smem + OFF_C);
    float* Bs    = reinterpret_cast<float*>(smem + OFF_B);

    // stage C (sum of 4 k-group partials) + bias into smem; hidden under prologue
#pragma unroll
    for (int i = 0; i < 3; ++i) {
        int e = tid + 256 * i;
        Cs[e] = g_pwCp[e] + g_pwCp[D + e] + g_pwCp[2 * D + e] + g_pwCp[3 * D + e];
        Bs[e] = bias[e];
    }

    // ---- phase-1 tiling ----
    const int wm1 = w & 1, wn1 = w >> 1;
    const int xr0 = tid >> 4, xc4 = tid & 15;
    const float* xbase = x + (m0 + xr0) * D + xc4 * 4;
    const uint32_t aoff1 = (wm1 * 32 + (lane & 7) + ((lane >> 3) & 1) * 8) * 80 + ((lane >> 4) & 1) * 16;
    const uint32_t boff1 = (wn1 * 64 + (lane & 7) + ((lane >> 4) & 1) * 8) * 80 + ((lane >> 3) & 1) * 16;

    float acc[2][8][4];
#pragma unroll
    for (int mt = 0; mt < 2; ++mt)
#pragma unroll
        for (int nt = 0; nt < 8; ++nt)
#pragma unroll
            for (int j = 0; j < 4; ++j) acc[mt][nt][j] = 0.f;

    float sq[4] = {0.f, 0.f, 0.f, 0.f};

    // ---- prologue: load + stage x chunk 0 directly, cp.async pn chunk 0 ----
    float4 R[4];
#pragma unroll
    for (int f = 0; f < 4; ++f)
        R[f] = *reinterpret_cast<const float4*>(xbase + f * 16 * D);
#pragma unroll
    for (int f = 0; f < 4; ++f) {
        float4 v = R[f];
        sq[f] += v.x * v.x + v.y * v.y + v.z * v.z + v.w * v.w;
        uint32_t word = (uint32_t)packe4m3(v.x, v.y) |
                        ((uint32_t)packe4m3(v.z, v.w) << 16);
        *reinterpret_cast<uint32_t*>(smem + OFF_XB0 + (xr0 + 16 * f) * 80 + xc4 * 4) = word;
    }
#pragma unroll
    for (int it = 0; it < 4; ++it) {
        int idx = tid + 256 * it;
        int row = idx >> 2, u = idx & 3;
        CP16(sb + OFF_PN0 + row * 80 + u * 16, g_pn8 + row * D + u * 16);
    }
    CP_COMMIT();

    // ---- Phase 1 (FP8): 12 K-chunks of 64; staging interleaved between MMA halves
    for (int c = 0; c < 12; ++c) {
        const int b = c & 1;
        const uint32_t XB = b ? (sb + OFF_XB1) : (sb + OFF_XB0);
        const uint32_t PN = b ? (sb + OFF_PN1) : (sb + OFF_PN0);
        CP_WAIT0();
        __syncthreads();                  // PN(c)+XB(c) visible; opposite buffers free
        if (c < 11) {
            const uint32_t PNn = b ? (sb + OFF_PN0) : (sb + OFF_PN1);
#pragma unroll
            for (int it = 0; it < 4; ++it) {
                int idx = tid + 256 * it;
                int row = idx >> 2, u = idx & 3;
                CP16(PNn + row * 80 + u * 16, g_pn8 + row * D + (c + 1) * 64 + u * 16);
            }
            CP_COMMIT();
#pragma unroll
            for (int f = 0; f < 4; ++f)
                R[f] = *reinterpret_cast<const float4*>(xbase + f * 16 * D + (c + 1) * 64);
        }
        // MMA half 1 (ks=0)
        {
            uint32_t a0[2], a1[2], a2[2], a3[2];
#pragma unroll
            for (int mt = 0; mt < 2; ++mt)
                ldsm_x4(a0[mt], a1[mt], a2[mt], a3[mt], XB + aoff1 + mt * 16 * 80);
#pragma unroll
            for (int p = 0; p < 4; ++p) {
                uint32_t b0, b1, b2, b3;
                ldsm_x4(b0, b1, b2, b3, PN + boff1 + p * 16 * 80);
#pragma unroll
                for (int mt = 0; mt < 2; ++mt) {
                    mma8(acc[mt][2 * p],     a0[mt], a1[mt], a2[mt], a3[mt], b0, b1);
                    mma8(acc[mt][2 * p + 1], a0[mt], a1[mt], a2[mt], a3[mt], b2, b3);
                }
            }
        }
        // staging of chunk c+1 into the opposite buffer (fills tensor drain)
        if (c < 11) {
            const uint32_t xoff = b ? OFF_XB0 : OFF_XB1;
#pragma unroll
            for (int f = 0; f < 4; ++f) {
                float4 v = R[f];
                sq[f] += v.x * v.x + v.y * v.y + v.z * v.z + v.w * v.w;
                uint32_t word = (uint32_t)packe4m3(v.x, v.y) |
                                ((uint32_t)packe4m3(v.z, v.w) << 16);
                *reinterpret_cast<uint32_t*>(smem + xoff + (xr0 + 16 * f) * 80 + xc4 * 4) = word;
            }
        } else {
            // final row-norm reduce (all 12 chunks' sq accumulated by staging at c=10)
#pragma unroll
            for (int f = 0; f < 4; ++f) {
                float s = sq[f];
                s += __shfl_xor_sync(0xffffffffu, s, 1);
                s += __shfl_xor_sync(0xffffffffu, s, 2);
                s += __shfl_xor_sync(0xffffffffu, s, 4);
                s += __shfl_xor_sync(0xffffffffu, s, 8);
                if ((tid & 15) == 0) inv[xr0 + 16 * f] = 1.f / fmaxf(sqrtf(s), 1e-12f);
            }
        }
        // MMA half 2 (ks=1)
        {
            uint32_t a0[2], a1[2], a2[2], a3[2];
#pragma unroll
            for (int mt = 0; mt < 2; ++mt)
                ldsm_x4(a0[mt], a1[mt], a2[mt], a3[mt], XB + aoff1 + mt * 16 * 80 + 32);
#pragma unroll
            for (int p = 0; p < 4; ++p) {
                uint32_t b0, b1, b2, b3;
                ldsm_x4(b0, b1, b2, b3, PN + boff1 + p * 16 * 80 + 32);
#pragma unroll
                for (int mt = 0; mt < 2; ++mt) {
                    mma8(acc[mt][2 * p],     a0[mt], a1[mt], a2[mt], a3[mt], b0, b1);
                    mma8(acc[mt][2 * p + 1], a0[mt], a1[mt], a2[mt], a3[mt], b2, b3);
                }
            }
        }
    }
    __syncthreads();   // phase-1 reads done; inv visible; overlay reusable

    // ---- kick off PW chunk 0 staging (overlaps softmax) ----
#pragma unroll
    for (int it = 0; it < 8; ++it) {
        int idx = tid + 256 * it;
        int row = idx >> 4, u = idx & 15;
        CP16(sb + OFF_PW0 + row * 272 + u * 16, g_pwt8 + row * KP + u * 16);
    }
    CP_COMMIT();

    // ---- softmax: e = exp(sim/||x||); store d = 64*(e-1) e4m3; sum e ----
#pragma unroll
    for (int mt = 0; mt < 2; ++mt) {
        const int r0 = wm1 * 32 + mt * 16 + g, r1 = r0 + 8;
        const float iv0 = inv[r0], iv1 = inv[r1];
        float s0 = 0.f, s1 = 0.f;
#pragma unroll
        for (int nt = 0; nt < 8; ++nt) {
            float e0 = __expf(acc[mt][nt][0] * iv0);
            float e1 = __expf(acc[mt][nt][1] * iv0);
            float e2 = __expf(acc[mt][nt][2] * iv1);
            float e3 = __expf(acc[mt][nt][3] * iv1);
            const uint32_t cb = wn1 * 64 + nt * 8 + 2 * q;
            *reinterpret_cast<uint16_t*>(smem + OFF_EXP + r0 * 272 + cb) =
                packe4m3(64.f * (e0 - 1.f), 64.f * (e1 - 1.f));
            *reinterpret_cast<uint16_t*>(smem + OFF_EXP + r1 * 272 + cb) =
                packe4m3(64.f * (e2 - 1.f), 64.f * (e3 - 1.f));
            s0 += e0 + e1; s1 += e2 + e3;
        }
        s0 += __shfl_xor_sync(0xffffffffu, s0, 1);
        s0 += __shfl_xor_sync(0xffffffffu, s0, 2);
        s1 += __shfl_xor_sync(0xffffffffu, s1, 1);
        s1 += __shfl_xor_sync(0xffffffffu, s1, 2);
        if (q == 0) { parts[wn1 * 64 + r0] = s0; parts[wn1 * 64 + r1] = s1; }
    }
    __syncthreads();
    if (tid < 64) {
        float s = parts[tid] + parts[64 + tid] + parts[128 + tid] + parts[192 + tid];
        invS[tid] = 1.f / (256.f * s);
    }

    // ---- Phase 3 (FP8 d-decomp): 6 e-chunks of 128, PW double-buffered ----
    const int wm3 = w & 1, wn3 = w >> 1;
    const uint32_t aoff3 = (wm3 * 32 + (lane & 7) + ((lane >> 3) & 1) * 8) * 272 + ((lane >> 4) & 1) * 16;
    const uint32_t boff3 = (wn3 * 32 + (lane & 7) + ((lane >> 4) & 1) * 8) * 272 + ((lane >> 3) & 1) * 16;
    const float inv4096 = 1.f / 4096.f;

    for (int j = 0; j < 6; ++j) {
        const uint32_t PW = (j & 1) ? (sb + OFF_PW1) : (sb + OFF_PW0);
        CP_WAIT0();
        __syncthreads();                  // PW(j) ready; other buffer's readers done
        if (j < 5) {                      // cp j+1 overlaps MMA(j) + epilogue(j)
            const uint32_t PWn = (j & 1) ? (sb + OFF_PW0) : (sb + OFF_PW1);
#pragma unroll
            for (int it = 0; it < 8; ++it) {
                int idx = tid + 256 * it;
                int row = idx >> 4, u = idx & 15;
                CP16(PWn + row * 272 + u * 16, g_pwt8 + ((j + 1) * 128 + row) * KP + u * 16);
            }
            CP_COMMIT();
        }
        float acc2[2][4][4];
#pragma unroll
        for (int mt = 0; mt < 2; ++mt)
#pragma unroll
            for (int nt = 0; nt < 4; ++nt)
#pragma unroll
                for (int jj = 0; jj < 4; ++jj) acc2[mt][nt][jj] = 0.f;

#pragma unroll
        for (int ks = 0; ks < 8; ++ks) {
            uint32_t b0, b1, b2, b3, b4, b5, b6, b7;
            ldsm_x4(b0, b1, b2, b3, PW + boff3 + ks * 32);
            ldsm_x4(b4, b5, b6, b7, PW + boff3 + 16 * 272 + ks * 32);
#pragma unroll
            for (int mt = 0; mt < 2; ++mt) {
                uint32_t a0, a1, a2, a3;
                ldsm_x4(a0, a1, a2, a3, sb + OFF_EXP + aoff3 + mt * 16 * 272 + ks * 32);
                mma8(acc2[mt][0], a0, a1, a2, a3, b0, b1);
                mma8(acc2[mt][1], a0, a1, a2, a3, b2, b3);
                mma8(acc2[mt][2], a0, a1, a2, a3, b4, b5);
                mma8(acc2[mt][3], a0, a1, a2, a3, b6, b7);
            }
        }
        // epilogue: out = (C + corr/4096) * invS + bias  (C, bias from smem)
#pragma unroll
        for (int mt = 0; mt < 2; ++mt) {
            const int r0 = wm3 * 32 + mt * 16 + g, r1 = r0 + 8;
            const float is0 = invS[r0], is1 = invS[r1];
#pragma unroll
            for (int nt = 0; nt < 4; ++nt) {
                const int cc = j * 128 + wn3 * 32 + nt * 8 + 2 * q;
                const float2 bv = *reinterpret_cast<const float2*>(Bs + cc);
                const float2 Cv = *reinterpret_cast<const float2*>(Cs + cc);
                *reinterpret_cast<float2*>(out + (m0 + r0) * D + cc) = make_float2(
                    (Cv.x + acc2[mt][nt][0] * inv4096) * is0 + bv.x,
                    (Cv.y + acc2[mt][nt][1] * inv4096) * is0 + bv.y);
                *reinterpret_cast<float2*>(out + (m0 + r1) * D + cc) = make_float2(
                    (Cv.x + acc2[mt][nt][2] * inv4096) * is1 + bv.x,
                    (Cv.y + acc2[mt][nt][3] * inv4096) * is1 + bv.y);
            }
        }
    }
}

// ---------------------------------------------------------------------------
extern "C" void kernel_launch(void* const* d_in, const int* in_sizes, int n_in,
                              void* d_out, int out_size) {
    const float* x = (const float*)d_in[0];
    const float* P = (const float*)d_in[1];
    const float* W = (const float*)d_in[2];
    const float* b = (const float*)d_in[3];
    float* out = (float*)d_out;

    cudaFuncSetAttribute(main_kernel, cudaFuncAttributeMaxDynamicSharedMemorySize, SMEM_MAIN);

    prep_kernel<<<448, 256>>>(P, W);

    int rows = in_sizes[0] / D;               // 131072
    main_kernel<<<rows / 64, 256, SMEM_MAIN>>>(x, b, out);
}